// round 1
// baseline (speedup 1.0000x reference)
#include <cuda_runtime.h>
#include <math.h>

#define NN 512
#define HH 512
#define XD 128

#define TI 4
#define TJ 32
#define NJT (NN/TJ)   /* 16 j-tiles  */
#define NIT (NN/TI)   /* 128 i-tiles */

// Scratch (allocation-free rule: __device__ globals)
__device__ float g_hx[NN*HH];        // hx[j][k]
__device__ float g_hyb[NN*HH];       // hy[i][k] + b1[k]
__device__ float g_partial[NN*NJT];  // per-(i, jtile) sum of exp(T1)
__device__ float g_t0[NN];           // diagonal T1[i][i]

// ---------------------------------------------------------------------------
// Prologue: hx = x @ W1x ; hyb = y @ W1y + b1    (both [512,512], K=128)
// grid (8,8,2), block 256. 64x64 tile, 4x4 per thread.
// ---------------------------------------------------------------------------
__global__ void __launch_bounds__(256) prologue_gemm(
    const float* __restrict__ x, const float* __restrict__ y,
    const float* __restrict__ w1x, const float* __restrict__ w1y,
    const float* __restrict__ b1)
{
    const float* A = (blockIdx.z == 0) ? x   : y;
    const float* B = (blockIdx.z == 0) ? w1x : w1y;
    float*       C = (blockIdx.z == 0) ? g_hx : g_hyb;

    int m0 = blockIdx.y * 64, n0 = blockIdx.x * 64;
    __shared__ float sA[16][64 + 2];
    __shared__ float sB[16][64 + 2];
    int tid = threadIdx.x;
    int ty = tid >> 4, tx = tid & 15;

    float acc[4][4] = {};
    for (int k0 = 0; k0 < XD; k0 += 16) {
        #pragma unroll
        for (int s = 0; s < 4; s++) {           // A chunk: 64 rows x 16 k
            int idx = tid + s * 256;
            int kk = idx & 15, m = idx >> 4;
            sA[kk][m] = A[(m0 + m) * XD + k0 + kk];
        }
        #pragma unroll
        for (int s = 0; s < 4; s++) {           // B chunk: 16 k x 64 cols
            int idx = tid + s * 256;
            int nn = idx & 63, kk = idx >> 6;
            sB[kk][nn] = B[(k0 + kk) * HH + n0 + nn];
        }
        __syncthreads();
        #pragma unroll
        for (int kk = 0; kk < 16; kk++) {
            float a[4], b[4];
            #pragma unroll
            for (int u = 0; u < 4; u++) a[u] = sA[kk][ty * 4 + u];
            #pragma unroll
            for (int v = 0; v < 4; v++) b[v] = sB[kk][tx * 4 + v];
            #pragma unroll
            for (int u = 0; u < 4; u++)
                #pragma unroll
                for (int v = 0; v < 4; v++)
                    acc[u][v] = fmaf(a[u], b[v], acc[u][v]);
        }
        __syncthreads();
    }
    #pragma unroll
    for (int u = 0; u < 4; u++)
        #pragma unroll
        for (int v = 0; v < 4; v++) {
            int m = m0 + ty * 4 + u, n = n0 + tx * 4 + v;
            float val = acc[u][v];
            if (blockIdx.z == 1) val += b1[n];
            C[m * HH + n] = val;
        }
}

// ---------------------------------------------------------------------------
// Main fused kernel. One CTA: (TI=4 i's) x (TJ=32 j's) = 128 rows of the
// implicit [N^2, H] matrix A[r,k] = relu(hx[j,k] + hyb[i,k]).
// Computes h2 = relu(A @ W2 + b2) 128 cols at a time, folds the W3 dot into
// a per-row scalar, then softplus / exp / per-i partial sums. Diagonal -> T0.
// grid (NJT, NIT), block 256. 8x8 register tile over 128x128.
// ---------------------------------------------------------------------------
__global__ void __launch_bounds__(256) main_kernel(
    const float* __restrict__ w2, const float* __restrict__ b2,
    const float* __restrict__ w3, const float* __restrict__ b3)
{
    int jt = blockIdx.x;   // 0..NJT-1
    int it = blockIdx.y;   // 0..NIT-1
    int tid = threadIdx.x;
    int ty = tid >> 4, tx = tid & 15;   // 16x16 threads, 8x8 each

    __shared__ float sA[16][128 + 4];
    __shared__ float sB[16][128 + 4];

    float pt[8];
    #pragma unroll
    for (int u = 0; u < 8; u++) pt[u] = 0.f;

    for (int nb = 0; nb < 4; nb++) {           // 4 blocks of 128 W2 columns
        float acc[8][8];
        #pragma unroll
        for (int u = 0; u < 8; u++)
            #pragma unroll
            for (int v = 0; v < 8; v++) acc[u][v] = 0.f;

        for (int k0 = 0; k0 < HH; k0 += 16) {
            // Generate A tile: sA[kk][r] = relu(hx[j,k]+hyb[i,k])
            #pragma unroll
            for (int s = 0; s < 8; s++) {
                int idx = tid + s * 256;
                int kk = idx & 15, r = idx >> 4;
                int i = it * TI + (r >> 5);
                int j = jt * TJ + (r & 31);
                float v = g_hx[j * HH + k0 + kk] + g_hyb[i * HH + k0 + kk];
                sA[kk][r] = fmaxf(v, 0.f);
            }
            // Load W2 tile: sB[kk][c]
            #pragma unroll
            for (int s = 0; s < 8; s++) {
                int idx = tid + s * 256;
                int c = idx & 127, kk = idx >> 7;
                sB[kk][c] = w2[(k0 + kk) * HH + nb * 128 + c];
            }
            __syncthreads();
            #pragma unroll
            for (int kk = 0; kk < 16; kk++) {
                float a[8], b[8];
                #pragma unroll
                for (int u = 0; u < 8; u++) a[u] = sA[kk][ty * 8 + u];
                #pragma unroll
                for (int v = 0; v < 8; v++) b[v] = sB[kk][tx * 8 + v];
                #pragma unroll
                for (int u = 0; u < 8; u++)
                    #pragma unroll
                    for (int v = 0; v < 8; v++)
                        acc[u][v] = fmaf(a[u], b[v], acc[u][v]);
            }
            __syncthreads();
        }
        // Fold this column block: pt[u] += sum_v relu(acc + b2) * w3
        #pragma unroll
        for (int v = 0; v < 8; v++) {
            int col = nb * 128 + tx * 8 + v;
            float b2c = b2[col], w3c = w3[col];
            #pragma unroll
            for (int u = 0; u < 8; u++) {
                float h = acc[u][v] + b2c;
                pt[u] = fmaf(fmaxf(h, 0.f), w3c, pt[u]);
            }
        }
    }

    // Reduce pt across the 16 tx-groups per row
    __shared__ float red[16][129];
    __shared__ float se[128];
    #pragma unroll
    for (int u = 0; u < 8; u++) red[tx][ty * 8 + u] = pt[u];
    __syncthreads();

    if (tid < 128) {
        int r = tid;
        float s = 0.f;
        #pragma unroll
        for (int xx = 0; xx < 16; xx++) s += red[xx][r];
        float uval = s + b3[0];
        float T1 = (uval > 20.f) ? uval : log1pf(expf(uval));
        int i = it * TI + (r >> 5);
        int j = jt * TJ + (r & 31);
        if (i == j) g_t0[i] = T1;        // exactly once per i across the grid
        se[r] = expf(T1);                // T1 in (0, ~few): exp is safe
    }
    __syncthreads();

    if (tid < TI) {
        float s = 0.f;
        #pragma unroll
        for (int jl = 0; jl < TJ; jl++) s += se[tid * TJ + jl];
        g_partial[(it * TI + tid) * NJT + jt] = s;
    }
}

// ---------------------------------------------------------------------------
// Finalize: result = mean_i(T0_i - log(sum_j exp T1_ij)) + log N
// ---------------------------------------------------------------------------
__global__ void finalize_kernel(float* __restrict__ out)
{
    int tid = threadIdx.x;   // 512 threads, one per i
    float s = 0.f;
    #pragma unroll
    for (int jt = 0; jt < NJT; jt++) s += g_partial[tid * NJT + jt];
    float val = g_t0[tid] - logf(s);

    __shared__ float sh[512];
    sh[tid] = val;
    __syncthreads();
    for (int off = 256; off > 0; off >>= 1) {
        if (tid < off) sh[tid] += sh[tid + off];
        __syncthreads();
    }
    if (tid == 0) out[0] = sh[0] / 512.f + logf(512.f);
}

extern "C" void kernel_launch(void* const* d_in, const int* in_sizes, int n_in,
                              void* d_out, int out_size)
{
    const float* x   = (const float*)d_in[0];
    const float* y   = (const float*)d_in[1];
    const float* w1x = (const float*)d_in[2];
    const float* w1y = (const float*)d_in[3];
    const float* b1  = (const float*)d_in[4];
    const float* w2  = (const float*)d_in[5];
    const float* b2  = (const float*)d_in[6];
    const float* w3  = (const float*)d_in[7];
    const float* b3  = (const float*)d_in[8];
    float* out = (float*)d_out;

    dim3 g1(8, 8, 2);
    prologue_gemm<<<g1, 256>>>(x, y, w1x, w1y, b1);
    dim3 g2(NJT, NIT);
    main_kernel<<<g2, 256>>>(w2, b2, w3, b3);
    finalize_kernel<<<1, 512>>>(out);
}

// round 3
// speedup vs baseline: 2.5300x; 2.5300x over previous
#include <cuda_runtime.h>
#include <cuda_fp16.h>
#include <math.h>
#include <stdint.h>

#define NN 512
#define HH 512
#define XD 128
#define NJT 16
#define NIT 128

// ---------------- device scratch ----------------
__device__ float  g_hx [NN*HH];
__device__ float  g_hyb[NN*HH];
__device__ __half g_w2h[HH*HH];    // W2^T hi,      [c*512 + k]
__device__ __half g_w2l[HH*HH];    // W2^T lo*1024, [c*512 + k]
__device__ float  g_partial[NN*NJT];
__device__ float  g_t0[NN];

// ---------------- helpers ----------------
__device__ __forceinline__ uint32_t smem_u32(const void* p) {
    uint32_t a;
    asm("{ .reg .u64 t; cvta.to.shared.u64 t, %1; cvt.u32.u64 %0, t; }" : "=r"(a) : "l"(p));
    return a;
}
__device__ __forceinline__ void ldsm4(uint32_t* r, uint32_t addr) {
    asm volatile("ldmatrix.sync.aligned.m8n8.x4.shared.b16 {%0,%1,%2,%3}, [%4];"
        : "=r"(r[0]), "=r"(r[1]), "=r"(r[2]), "=r"(r[3]) : "r"(addr));
}
__device__ __forceinline__ void ldsm2(uint32_t& r0, uint32_t& r1, uint32_t addr) {
    asm volatile("ldmatrix.sync.aligned.m8n8.x2.shared.b16 {%0,%1}, [%2];"
        : "=r"(r0), "=r"(r1) : "r"(addr));
}
__device__ __forceinline__ void mma16816(float* d, const uint32_t* a, uint32_t b0, uint32_t b1) {
    asm volatile("mma.sync.aligned.m16n8k16.row.col.f32.f16.f16.f32 "
        "{%0,%1,%2,%3}, {%4,%5,%6,%7}, {%8,%9}, {%0,%1,%2,%3};"
        : "+f"(d[0]), "+f"(d[1]), "+f"(d[2]), "+f"(d[3])
        : "r"(a[0]), "r"(a[1]), "r"(a[2]), "r"(a[3]), "r"(b0), "r"(b1));
}

// ---------------------------------------------------------------------------
// Prologue: hx = x @ W1x ; hyb = y @ W1y + b1
// ---------------------------------------------------------------------------
__global__ void __launch_bounds__(256) prologue_gemm(
    const float* __restrict__ x, const float* __restrict__ y,
    const float* __restrict__ w1x, const float* __restrict__ w1y,
    const float* __restrict__ b1)
{
    const float* A = (blockIdx.z == 0) ? x   : y;
    const float* B = (blockIdx.z == 0) ? w1x : w1y;
    float*       C = (blockIdx.z == 0) ? g_hx : g_hyb;

    int m0 = blockIdx.y * 64, n0 = blockIdx.x * 64;
    __shared__ float sA[16][64 + 2];
    __shared__ float sB[16][64 + 2];
    int tid = threadIdx.x;
    int ty = tid >> 4, tx = tid & 15;

    float acc[4][4] = {};
    for (int k0 = 0; k0 < XD; k0 += 16) {
        #pragma unroll
        for (int s = 0; s < 4; s++) {
            int idx = tid + s * 256;
            int kk = idx & 15, m = idx >> 4;
            sA[kk][m] = A[(m0 + m) * XD + k0 + kk];
        }
        #pragma unroll
        for (int s = 0; s < 4; s++) {
            int idx = tid + s * 256;
            int nn = idx & 63, kk = idx >> 6;
            sB[kk][nn] = B[(k0 + kk) * HH + n0 + nn];
        }
        __syncthreads();
        #pragma unroll
        for (int kk = 0; kk < 16; kk++) {
            float a[4], b[4];
            #pragma unroll
            for (int u = 0; u < 4; u++) a[u] = sA[kk][ty * 4 + u];
            #pragma unroll
            for (int v = 0; v < 4; v++) b[v] = sB[kk][tx * 4 + v];
            #pragma unroll
            for (int u = 0; u < 4; u++)
                #pragma unroll
                for (int v = 0; v < 4; v++)
                    acc[u][v] = fmaf(a[u], b[v], acc[u][v]);
        }
        __syncthreads();
    }
    #pragma unroll
    for (int u = 0; u < 4; u++)
        #pragma unroll
        for (int v = 0; v < 4; v++) {
            int m = m0 + ty * 4 + u, n = n0 + tx * 4 + v;
            float val = acc[u][v];
            if (blockIdx.z == 1) val += b1[n];
            C[m * HH + n] = val;
        }
}

// ---------------------------------------------------------------------------
// W2 transpose + fp16 hi/lo split (lo scaled by 1024)
// ---------------------------------------------------------------------------
__global__ void __launch_bounds__(512) w2split_kernel(const float* __restrict__ w2)
{
    int k = blockIdx.x;
    int c = threadIdx.x;
    float w = w2[k * HH + c];
    __half h = __float2half_rn(w);
    __half l = __float2half_rn((w - __half2float(h)) * 1024.f);
    g_w2h[c * HH + k] = h;
    g_w2l[c * HH + k] = l;
}

// ---------------------------------------------------------------------------
// Main HMMA kernel.
// grid (16, 128), 256 threads (8 warps, 4 m-warps x 2 n-warps).
// CTA tile: 128 rows x 128 cols (nb loop over 4 col blocks), K stages of 32.
// Stage smem layout (stride 80B/row -> ldmatrix conflict-free):
//   +0      A hi  (128 rows x 32 k halves)
//   +10240  A lo
//   +20480  B hi  (128 cols x 32 k halves)
//   +30720  B lo
// Two stages (81920 B) + b2/w3/reduction arrays.
// ---------------------------------------------------------------------------
#define STG 40960
#define SMEM_MAIN (81920 + 2048 + 2048 + 1024 + 512)

struct Pref {
    float4 xa[4], ya[4];
    uint4  bh[2], bl[2];
};

__device__ __forceinline__ void pref_load(Pref& p,
    const float* __restrict__ hx, const float* __restrict__ hy,
    const __half* __restrict__ wh, const __half* __restrict__ wl, int kc)
{
    const float4* a = (const float4*)(hx + kc * 32);
    const float4* b = (const float4*)(hy + kc * 32);
    #pragma unroll
    for (int i = 0; i < 4; i++) { p.xa[i] = a[i]; p.ya[i] = b[i]; }
    const uint4* whp = (const uint4*)(wh + kc * 32);
    const uint4* wlp = (const uint4*)(wl + kc * 32);
    p.bh[0] = whp[0]; p.bh[1] = whp[1];
    p.bl[0] = wlp[0]; p.bl[1] = wlp[1];
}

__device__ __forceinline__ void pref_store(const Pref& p, char* base, int fr, int fh)
{
    float v[16];
    #pragma unroll
    for (int i = 0; i < 4; i++) {
        v[i*4+0] = fmaxf(p.xa[i].x + p.ya[i].x, 0.f);
        v[i*4+1] = fmaxf(p.xa[i].y + p.ya[i].y, 0.f);
        v[i*4+2] = fmaxf(p.xa[i].z + p.ya[i].z, 0.f);
        v[i*4+3] = fmaxf(p.xa[i].w + p.ya[i].w, 0.f);
    }
    __half2 hi[8], lo[8];
    #pragma unroll
    for (int i = 0; i < 8; i++) {
        __half2 h = __floats2half2_rn(v[2*i], v[2*i+1]);
        float2 f = __half22float2(h);
        hi[i] = h;
        lo[i] = __floats2half2_rn((v[2*i] - f.x) * 1024.f, (v[2*i+1] - f.y) * 1024.f);
    }
    uint32_t off = fr * 80 + fh * 32;
    *(uint4*)(base + off)              = ((const uint4*)hi)[0];
    *(uint4*)(base + off + 16)         = ((const uint4*)hi)[1];
    *(uint4*)(base + 10240 + off)      = ((const uint4*)lo)[0];
    *(uint4*)(base + 10240 + off + 16) = ((const uint4*)lo)[1];
    *(uint4*)(base + 20480 + off)      = p.bh[0];
    *(uint4*)(base + 20480 + off + 16) = p.bh[1];
    *(uint4*)(base + 30720 + off)      = p.bl[0];
    *(uint4*)(base + 30720 + off + 16) = p.bl[1];
}

__global__ void __launch_bounds__(256, 1) main_mma(
    const float* __restrict__ b2, const float* __restrict__ w3,
    const float* __restrict__ b3)
{
    extern __shared__ char smem[];
    uint32_t sb = smem_u32(smem);
    int tid = threadIdx.x, lane = tid & 31, wid = tid >> 5;
    int warp_m = wid >> 1, warp_n = wid & 1;
    int jt = blockIdx.x, it = blockIdx.y;

    float* b2s  = (float*)(smem + 81920);
    float* w3s  = (float*)(smem + 81920 + 2048);
    float* sRow = (float*)(smem + 81920 + 4096);          // [128][2]
    float* sE   = (float*)(smem + 81920 + 4096 + 1024);   // [128]
    for (int c = tid; c < HH; c += 256) { b2s[c] = b2[c]; w3s[c] = w3[c]; }

    // fill mapping: thread -> (row fr, k-half fh)
    int fr = tid >> 1, fh = tid & 1;
    int f_jj = jt * 32 + (fr & 31);
    int f_ii = it * 4 + (fr >> 5);
    const float* hxp = g_hx  + f_jj * HH + fh * 16;
    const float* hyp = g_hyb + f_ii * HH + fh * 16;

    float ptl[4] = {0.f, 0.f, 0.f, 0.f};

    for (int nb = 0; nb < 4; nb++) {
        const __half* w2hp = g_w2h + (nb * 128 + fr) * HH + fh * 16;
        const __half* w2lp = g_w2l + (nb * 128 + fr) * HH + fh * 16;

        float accm[2][8][4] = {};
        float acca[2][8][4] = {};

        Pref p;
        pref_load(p, hxp, hyp, w2hp, w2lp, 0);
        pref_store(p, smem, fr, fh);
        __syncthreads();

        for (int kc = 0; kc < 16; kc++) {
            if (kc < 15) pref_load(p, hxp, hyp, w2hp, w2lp, kc + 1);

            uint32_t sA = sb + (kc & 1) * STG;
            #pragma unroll
            for (int ks = 0; ks < 2; ks++) {
                uint32_t ah[2][4], al[2][4];
                int arow = warp_m * 32 + ((lane >> 3) & 1) * 8 + (lane & 7);
                int achunk = ks * 2 + (lane >> 4);
                #pragma unroll
                for (int tm = 0; tm < 2; tm++) {
                    uint32_t ad = sA + (uint32_t)((arow + tm * 16) * 80 + achunk * 16);
                    ldsm4(ah[tm], ad);
                    ldsm4(al[tm], ad + 10240);
                }
                int bl8 = lane & 15;
                int bc = warp_n * 64 + (bl8 & 7);
                int bchunk = ks * 2 + (bl8 >> 3);
                #pragma unroll
                for (int tn = 0; tn < 8; tn++) {
                    uint32_t bd = sA + 20480u + (uint32_t)((bc + tn * 8) * 80 + bchunk * 16);
                    uint32_t bh0, bh1, bl0, bl1;
                    ldsm2(bh0, bh1, bd);
                    ldsm2(bl0, bl1, bd + 10240);
                    #pragma unroll
                    for (int tm = 0; tm < 2; tm++) {
                        mma16816(accm[tm][tn], ah[tm], bh0, bh1);
                        mma16816(acca[tm][tn], al[tm], bh0, bh1);
                        mma16816(acca[tm][tn], ah[tm], bl0, bl1);
                    }
                }
            }

            if (kc < 15) pref_store(p, smem + ((kc + 1) & 1) * STG, fr, fh);
            __syncthreads();
        }

        // fold this col block: ptl += relu(main + aux/1024 + b2) * w3
        #pragma unroll
        for (int tm = 0; tm < 2; tm++)
            #pragma unroll
            for (int tn = 0; tn < 8; tn++) {
                int c0 = nb * 128 + warp_n * 64 + tn * 8 + (lane & 3) * 2;
                float w3a = w3s[c0], w3b = w3s[c0 + 1];
                float b2a = b2s[c0], b2b = b2s[c0 + 1];
                float v0 = accm[tm][tn][0] + acca[tm][tn][0] * (1.f/1024.f) + b2a;
                float v1 = accm[tm][tn][1] + acca[tm][tn][1] * (1.f/1024.f) + b2b;
                float v2 = accm[tm][tn][2] + acca[tm][tn][2] * (1.f/1024.f) + b2a;
                float v3 = accm[tm][tn][3] + acca[tm][tn][3] * (1.f/1024.f) + b2b;
                ptl[tm*2+0] = fmaf(fmaxf(v0, 0.f), w3a, fmaf(fmaxf(v1, 0.f), w3b, ptl[tm*2+0]));
                ptl[tm*2+1] = fmaf(fmaxf(v2, 0.f), w3a, fmaf(fmaxf(v3, 0.f), w3b, ptl[tm*2+1]));
            }
        __syncthreads();
    }

    // reduce across the 4 column-thread groups (same rows)
    #pragma unroll
    for (int u = 0; u < 4; u++) {
        ptl[u] += __shfl_xor_sync(0xffffffffu, ptl[u], 1);
        ptl[u] += __shfl_xor_sync(0xffffffffu, ptl[u], 2);
    }
    if ((lane & 3) == 0) {
        int q = lane >> 2;
        sRow[(warp_m * 32 +  0 + q) * 2 + warp_n] = ptl[0];
        sRow[(warp_m * 32 +  8 + q) * 2 + warp_n] = ptl[1];
        sRow[(warp_m * 32 + 16 + q) * 2 + warp_n] = ptl[2];
        sRow[(warp_m * 32 + 24 + q) * 2 + warp_n] = ptl[3];
    }
    __syncthreads();

    if (tid < 128) {
        float s = sRow[tid * 2] + sRow[tid * 2 + 1] + b3[0];
        float T1 = (s > 20.f) ? s : log1pf(expf(s));
        int ii = it * 4 + (tid >> 5);
        int jj = jt * 32 + (tid & 31);
        if (ii == jj) g_t0[ii] = T1;
        sE[tid] = expf(T1);
    }
    __syncthreads();

    if (tid < 4) {
        float s = 0.f;
        #pragma unroll
        for (int jl = 0; jl < 32; jl++) s += sE[tid * 32 + jl];
        g_partial[(it * 4 + tid) * NJT + jt] = s;
    }
}

// ---------------------------------------------------------------------------
// Finalize
// ---------------------------------------------------------------------------
__global__ void finalize_kernel(float* __restrict__ out)
{
    int tid = threadIdx.x;
    float s = 0.f;
    #pragma unroll
    for (int jt = 0; jt < NJT; jt++) s += g_partial[tid * NJT + jt];
    float val = g_t0[tid] - logf(s);

    __shared__ float sh[512];
    sh[tid] = val;
    __syncthreads();
    for (int off = 256; off > 0; off >>= 1) {
        if (tid < off) sh[tid] += sh[tid + off];
        __syncthreads();
    }
    if (tid == 0) out[0] = sh[0] / 512.f + logf(512.f);
}

extern "C" void kernel_launch(void* const* d_in, const int* in_sizes, int n_in,
                              void* d_out, int out_size)
{
    const float* x   = (const float*)d_in[0];
    const float* y   = (const float*)d_in[1];
    const float* w1x = (const float*)d_in[2];
    const float* w1y = (const float*)d_in[3];
    const float* b1  = (const float*)d_in[4];
    const float* w2  = (const float*)d_in[5];
    const float* b2  = (const float*)d_in[6];
    const float* w3  = (const float*)d_in[7];
    const float* b3  = (const float*)d_in[8];
    float* out = (float*)d_out;

    cudaFuncSetAttribute(main_mma, cudaFuncAttributeMaxDynamicSharedMemorySize, SMEM_MAIN);

    dim3 g1(8, 8, 2);
    prologue_gemm<<<g1, 256>>>(x, y, w1x, w1y, b1);
    w2split_kernel<<<HH, HH>>>(w2);
    dim3 g2(NJT, NIT);
    main_mma<<<g2, 256, SMEM_MAIN>>>(b2, w3, b3);
    finalize_kernel<<<1, 512>>>(out);
}

// round 5
// speedup vs baseline: 2.7558x; 1.0893x over previous
#include <cuda_runtime.h>
#include <cuda_fp16.h>
#include <math.h>
#include <stdint.h>

#define NN 512
#define HH 512
#define XD 128
#define NJT 16
#define NIT 128

#define HXS 520            /* padded row stride (floats) for hx/hyb smem */

// smem byte offsets
#define OFF_HX   0
#define OFF_HYB  66560
#define OFF_B    74880     /* two stages of 20480 (hi at +0, lo at +10240) */
#define OFF_B2   115840
#define OFF_W3   117888
#define OFF_ROW  119936
#define OFF_E    120960
#define SMEM_MAIN 121472
#define BSTG 20480

// ---------------- device scratch ----------------
__device__ float  g_hx [NN*HH];
__device__ float  g_hyb[NN*HH];
__device__ __half g_w2h[HH*HH];    // W2^T hi,      [c*512 + k]
__device__ __half g_w2l[HH*HH];    // W2^T lo*1024
__device__ float  g_partial[NN*NJT];
__device__ float  g_t0[NN];

// ---------------- helpers ----------------
__device__ __forceinline__ uint32_t smem_u32(const void* p) {
    uint32_t a;
    asm("{ .reg .u64 t; cvta.to.shared.u64 t, %1; cvt.u32.u64 %0, t; }" : "=r"(a) : "l"(p));
    return a;
}
__device__ __forceinline__ void ldsm4(uint32_t* r, uint32_t addr) {
    asm volatile("ldmatrix.sync.aligned.m8n8.x4.shared.b16 {%0,%1,%2,%3}, [%4];"
        : "=r"(r[0]), "=r"(r[1]), "=r"(r[2]), "=r"(r[3]) : "r"(addr));
}
__device__ __forceinline__ void mma16816(float* d, const uint32_t* a, uint32_t b0, uint32_t b1) {
    asm volatile("mma.sync.aligned.m16n8k16.row.col.f32.f16.f16.f32 "
        "{%0,%1,%2,%3}, {%4,%5,%6,%7}, {%8,%9}, {%0,%1,%2,%3};"
        : "+f"(d[0]), "+f"(d[1]), "+f"(d[2]), "+f"(d[3])
        : "r"(a[0]), "r"(a[1]), "r"(a[2]), "r"(a[3]), "r"(b0), "r"(b1));
}
__device__ __forceinline__ void cp16(uint32_t dst, const void* src) {
    asm volatile("cp.async.cg.shared.global [%0], [%1], 16;" :: "r"(dst), "l"(src));
}
#define CP_COMMIT() asm volatile("cp.async.commit_group;" ::: "memory")
#define CP_WAIT1()  asm volatile("cp.async.wait_group 1;" ::: "memory")
#define CP_WAIT0()  asm volatile("cp.async.wait_group 0;" ::: "memory")

// split v0,v1 into hi half2 + lo*1024 half2
__device__ __forceinline__ void split2(float v0, float v1, uint32_t& hi, uint32_t& lo) {
    __half2 h = __floats2half2_rn(v0, v1);
    float2 f = __half22float2(h);
    __half2 l = __floats2half2_rn((v0 - f.x) * 1024.f, (v1 - f.y) * 1024.f);
    hi = *(uint32_t*)&h;
    lo = *(uint32_t*)&l;
}

// ---------------------------------------------------------------------------
// Prologue: hx = x @ W1x ; hyb = y @ W1y + b1
// ---------------------------------------------------------------------------
__global__ void __launch_bounds__(256) prologue_gemm(
    const float* __restrict__ x, const float* __restrict__ y,
    const float* __restrict__ w1x, const float* __restrict__ w1y,
    const float* __restrict__ b1)
{
    const float* A = (blockIdx.z == 0) ? x   : y;
    const float* B = (blockIdx.z == 0) ? w1x : w1y;
    float*       C = (blockIdx.z == 0) ? g_hx : g_hyb;

    int m0 = blockIdx.y * 64, n0 = blockIdx.x * 64;
    __shared__ float sA[16][64 + 2];
    __shared__ float sB[16][64 + 2];
    int tid = threadIdx.x;
    int ty = tid >> 4, tx = tid & 15;

    float acc[4][4] = {};
    for (int k0 = 0; k0 < XD; k0 += 16) {
        #pragma unroll
        for (int s = 0; s < 4; s++) {
            int idx = tid + s * 256;
            int kk = idx & 15, m = idx >> 4;
            sA[kk][m] = A[(m0 + m) * XD + k0 + kk];
        }
        #pragma unroll
        for (int s = 0; s < 4; s++) {
            int idx = tid + s * 256;
            int nn = idx & 63, kk = idx >> 6;
            sB[kk][nn] = B[(k0 + kk) * HH + n0 + nn];
        }
        __syncthreads();
        #pragma unroll
        for (int kk = 0; kk < 16; kk++) {
            float a[4], b[4];
            #pragma unroll
            for (int u = 0; u < 4; u++) a[u] = sA[kk][ty * 4 + u];
            #pragma unroll
            for (int v = 0; v < 4; v++) b[v] = sB[kk][tx * 4 + v];
            #pragma unroll
            for (int u = 0; u < 4; u++)
                #pragma unroll
                for (int v = 0; v < 4; v++)
                    acc[u][v] = fmaf(a[u], b[v], acc[u][v]);
        }
        __syncthreads();
    }
    #pragma unroll
    for (int u = 0; u < 4; u++)
        #pragma unroll
        for (int v = 0; v < 4; v++) {
            int m = m0 + ty * 4 + u, n = n0 + tx * 4 + v;
            float val = acc[u][v];
            if (blockIdx.z == 1) val += b1[n];
            C[m * HH + n] = val;
        }
}

// ---------------------------------------------------------------------------
// W2 transpose + fp16 hi/lo split
// ---------------------------------------------------------------------------
__global__ void __launch_bounds__(512) w2split_kernel(const float* __restrict__ w2)
{
    int k = blockIdx.x;
    int c = threadIdx.x;
    float w = w2[k * HH + c];
    __half h = __float2half_rn(w);
    __half l = __float2half_rn((w - __half2float(h)) * 1024.f);
    g_w2h[c * HH + k] = h;
    g_w2l[c * HH + k] = l;
}

// ---------------------------------------------------------------------------
// Main HMMA kernel. grid (16, 128), 256 threads, 8 warps (4 m x 2 n).
// hx/hyb staged in smem once; A fragments built in registers (hi/lo split);
// B (pre-split W2^T) double-buffered via cp.async, read via paired ldsm.x4.
// ---------------------------------------------------------------------------
__global__ void __launch_bounds__(256, 1) main_mma(
    const float* __restrict__ b2, const float* __restrict__ w3,
    const float* __restrict__ b3)
{
    extern __shared__ char smem[];
    uint32_t sb = smem_u32(smem);
    int tid = threadIdx.x, lane = tid & 31, wid = tid >> 5;
    int warp_m = wid >> 1, warp_n = wid & 1;
    int jt = blockIdx.x, it = blockIdx.y;

    float* hx_s  = (float*)(smem + OFF_HX);
    float* hyb_s = (float*)(smem + OFF_HYB);
    float* b2s   = (float*)(smem + OFF_B2);
    float* w3s   = (float*)(smem + OFF_W3);
    float* sRow  = (float*)(smem + OFF_ROW);
    float* sE    = (float*)(smem + OFF_E);

    // ---- group 0: stage hx (32 rows), hyb (4 rows), B stage for step 0 ----
    #pragma unroll
    for (int u = 0; u < 16; u++) {
        int idx = tid + u * 256;             // 4096 chunks of 16B
        int row = idx >> 7, q = idx & 127;
        cp16(sb + OFF_HX + (uint32_t)(row * (HXS*4) + q * 16),
             g_hx + (jt * 32 + row) * HH + q * 4);
    }
    #pragma unroll
    for (int u = 0; u < 2; u++) {
        int idx = tid + u * 256;             // 512 chunks
        int row = idx >> 7, q = idx & 127;
        cp16(sb + OFF_HYB + (uint32_t)(row * (HXS*4) + q * 16),
             g_hyb + (it * 4 + row) * HH + q * 4);
    }
    {   // B step 0 (nb=0, kc=0)
        #pragma unroll
        for (int u = 0; u < 4; u++) {
            int idx = tid + u * 256;         // 1024 chunks
            int part = idx >> 9, rem = idx & 511;
            int col = rem >> 2, q = rem & 3;
            const __half* src = (part ? g_w2l : g_w2h) + col * HH + q * 8;
            cp16(sb + OFF_B + (uint32_t)(part * 10240 + col * 80 + q * 16), src);
        }
    }
    CP_COMMIT();

    for (int c = tid; c < HH; c += 256) { b2s[c] = b2[c]; w3s[c] = w3[c]; }

    const int g  = lane >> 2;          // 0..7
    const int qk = (lane & 3) * 2;     // 0,2,4,6
    const float* hyr = hyb_s + warp_m * HXS;

    float ptl[4] = {0.f, 0.f, 0.f, 0.f};
    float accm[2][8][4];
    float acca[2][8][4];

    for (int s = 0; s < 64; s++) {
        int nb = s >> 4, kc = s & 15;
        if (kc == 0) {
            #pragma unroll
            for (int tm = 0; tm < 2; tm++)
                #pragma unroll
                for (int tn = 0; tn < 8; tn++)
                    #pragma unroll
                    for (int v = 0; v < 4; v++) { accm[tm][tn][v] = 0.f; acca[tm][tn][v] = 0.f; }
        }

        // prefetch B for step s+1
        if (s < 63) {
            int nb2 = (s + 1) >> 4, kc2 = (s + 1) & 15;
            uint32_t stg = sb + OFF_B + ((s + 1) & 1) * BSTG;
            #pragma unroll
            for (int u = 0; u < 4; u++) {
                int idx = tid + u * 256;
                int part = idx >> 9, rem = idx & 511;
                int col = rem >> 2, q = rem & 3;
                const __half* src = (part ? g_w2l : g_w2h)
                    + (nb2 * 128 + col) * HH + kc2 * 32 + q * 8;
                cp16(stg + (uint32_t)(part * 10240 + col * 80 + q * 16), src);
            }
            CP_COMMIT();
            CP_WAIT1();
        } else {
            CP_WAIT0();
        }
        __syncthreads();

        uint32_t stage = sb + OFF_B + (s & 1) * BSTG;

        #pragma unroll
        for (int ks = 0; ks < 2; ks++) {
            int kb = kc * 32 + ks * 16;
            // ---- A fragments in registers (hi/lo split) ----
            uint32_t ah[2][4], al[2][4];
            #pragma unroll
            for (int tm = 0; tm < 2; tm++) {
                int r0 = (warp_m * 32 + tm * 16 + g) & 31;       // j-local rows
                int r1 = (warp_m * 32 + tm * 16 + 8 + g) & 31;
                float2 x00 = *(const float2*)(hx_s + r0 * HXS + kb + qk);
                float2 x01 = *(const float2*)(hx_s + r0 * HXS + kb + qk + 8);
                float2 x10 = *(const float2*)(hx_s + r1 * HXS + kb + qk);
                float2 x11 = *(const float2*)(hx_s + r1 * HXS + kb + qk + 8);
                float2 y0  = *(const float2*)(hyr + kb + qk);
                float2 y1  = *(const float2*)(hyr + kb + qk + 8);
                split2(fmaxf(x00.x + y0.x, 0.f), fmaxf(x00.y + y0.y, 0.f), ah[tm][0], al[tm][0]);
                split2(fmaxf(x10.x + y0.x, 0.f), fmaxf(x10.y + y0.y, 0.f), ah[tm][1], al[tm][1]);
                split2(fmaxf(x01.x + y1.x, 0.f), fmaxf(x01.y + y1.y, 0.f), ah[tm][2], al[tm][2]);
                split2(fmaxf(x11.x + y1.x, 0.f), fmaxf(x11.y + y1.y, 0.f), ah[tm][3], al[tm][3]);
            }
            // ---- B tiles: paired ldsm.x4, 2 tn per op ----
            uint32_t bcol = (uint32_t)(warp_n * 64 + (lane & 7) + ((lane >> 4) & 1) * 8);
            uint32_t bchk = (uint32_t)(ks * 2 + ((lane >> 3) & 1));
            #pragma unroll
            for (int p = 0; p < 4; p++) {
                uint32_t addr = stage + (bcol + p * 16) * 80 + bchk * 16;
                uint32_t bh[4], bl[4];
                ldsm4(bh, addr);
                ldsm4(bl, addr + 10240);
                #pragma unroll
                for (int tm = 0; tm < 2; tm++) {
                    mma16816(accm[tm][2*p],   ah[tm], bh[0], bh[1]);
                    mma16816(accm[tm][2*p+1], ah[tm], bh[2], bh[3]);
                    mma16816(acca[tm][2*p],   al[tm], bh[0], bh[1]);
                    mma16816(acca[tm][2*p+1], al[tm], bh[2], bh[3]);
                    mma16816(acca[tm][2*p],   ah[tm], bl[0], bl[1]);
                    mma16816(acca[tm][2*p+1], ah[tm], bl[2], bl[3]);
                }
            }
        }
        __syncthreads();

        // ---- end of nb block: fold into per-row scalars ----
        if (kc == 15) {
            #pragma unroll
            for (int tm = 0; tm < 2; tm++)
                #pragma unroll
                for (int tn = 0; tn < 8; tn++) {
                    int c0 = nb * 128 + warp_n * 64 + tn * 8 + (lane & 3) * 2;
                    float w3a = w3s[c0], w3b = w3s[c0 + 1];
                    float b2a = b2s[c0], b2b = b2s[c0 + 1];
                    float v0 = accm[tm][tn][0] + acca[tm][tn][0] * (1.f/1024.f) + b2a;
                    float v1 = accm[tm][tn][1] + acca[tm][tn][1] * (1.f/1024.f) + b2b;
                    float v2 = accm[tm][tn][2] + acca[tm][tn][2] * (1.f/1024.f) + b2a;
                    float v3 = accm[tm][tn][3] + acca[tm][tn][3] * (1.f/1024.f) + b2b;
                    ptl[tm*2+0] = fmaf(fmaxf(v0, 0.f), w3a, fmaf(fmaxf(v1, 0.f), w3b, ptl[tm*2+0]));
                    ptl[tm*2+1] = fmaf(fmaxf(v2, 0.f), w3a, fmaf(fmaxf(v3, 0.f), w3b, ptl[tm*2+1]));
                }
        }
    }

    // ---- reduce across the 4 column-thread groups (same rows) ----
    #pragma unroll
    for (int u = 0; u < 4; u++) {
        ptl[u] += __shfl_xor_sync(0xffffffffu, ptl[u], 1);
        ptl[u] += __shfl_xor_sync(0xffffffffu, ptl[u], 2);
    }
    if ((lane & 3) == 0) {
        int q = lane >> 2;
        sRow[(warp_m * 32 +  0 + q) * 2 + warp_n] = ptl[0];
        sRow[(warp_m * 32 +  8 + q) * 2 + warp_n] = ptl[1];
        sRow[(warp_m * 32 + 16 + q) * 2 + warp_n] = ptl[2];
        sRow[(warp_m * 32 + 24 + q) * 2 + warp_n] = ptl[3];
    }
    __syncthreads();

    if (tid < 128) {
        float ssum = sRow[tid * 2] + sRow[tid * 2 + 1] + b3[0];
        float T1 = (ssum > 20.f) ? ssum : log1pf(expf(ssum));
        int ii = it * 4 + (tid >> 5);
        int jj = jt * 32 + (tid & 31);
        if (ii == jj) g_t0[ii] = T1;
        sE[tid] = expf(T1);
    }
    __syncthreads();

    if (tid < 4) {
        float ssum = 0.f;
        #pragma unroll
        for (int jl = 0; jl < 32; jl++) ssum += sE[tid * 32 + jl];
        g_partial[(it * 4 + tid) * NJT + jt] = ssum;
    }
}

// ---------------------------------------------------------------------------
// Finalize
// ---------------------------------------------------------------------------
__global__ void finalize_kernel(float* __restrict__ out)
{
    int tid = threadIdx.x;
    float s = 0.f;
    #pragma unroll
    for (int jt = 0; jt < NJT; jt++) s += g_partial[tid * NJT + jt];
    float val = g_t0[tid] - logf(s);

    __shared__ float sh[512];
    sh[tid] = val;
    __syncthreads();
    for (int off = 256; off > 0; off >>= 1) {
        if (tid < off) sh[tid] += sh[tid + off];
        __syncthreads();
    }
    if (tid == 0) out[0] = sh[0] / 512.f + logf(512.f);
}

extern "C" void kernel_launch(void* const* d_in, const int* in_sizes, int n_in,
                              void* d_out, int out_size)
{
    const float* x   = (const float*)d_in[0];
    const float* y   = (const float*)d_in[1];
    const float* w1x = (const float*)d_in[2];
    const float* w1y = (const float*)d_in[3];
    const float* b1  = (const float*)d_in[4];
    const float* w2  = (const float*)d_in[5];
    const float* b2  = (const float*)d_in[6];
    const float* w3  = (const float*)d_in[7];
    const float* b3  = (const float*)d_in[8];
    float* out = (float*)d_out;

    cudaFuncSetAttribute(main_mma, cudaFuncAttributeMaxDynamicSharedMemorySize, SMEM_MAIN);

    dim3 g1(8, 8, 2);
    prologue_gemm<<<g1, 256>>>(x, y, w1x, w1y, b1);
    w2split_kernel<<<HH, HH>>>(w2);
    dim3 g2(NJT, NIT);
    main_mma<<<g2, 256, SMEM_MAIN>>>(b2, w3, b3);
    finalize_kernel<<<1, 512>>>(out);
}

// round 7
// speedup vs baseline: 7.4001x; 2.6853x over previous
#include <cuda_runtime.h>
#include <cuda_fp16.h>
#include <math.h>
#include <stdint.h>

#define NN 512
#define HH 512
#define XD 128
#define NJT 16
#define NIT 128

#define HXS 520            /* padded row stride (floats) for hx/hyb smem */

// smem byte offsets (per CTA total 100992 B -> 2 CTAs/SM)
#define OFF_HX   0          /* 32 rows x 520 x 4 = 66560 */
#define OFF_HYB  66560      /* 4 rows x 520 x 4 = 8320   */
#define OFF_B    74880      /* 2 stages x 10240          */
#define OFF_B2   95360
#define OFF_W3   97408
#define OFF_ROW  99456
#define OFF_E    100480
#define SMEM_MAIN 100992
#define BSTG 10240

// ---------------- device scratch ----------------
__device__ float  g_hx [NN*HH];
__device__ float  g_hyb[NN*HH];
__device__ __half g_w2t[HH*HH];    // W2^T fp16, [c*512 + k]
__device__ float  g_partial[NN*NJT];
__device__ float  g_t0[NN];

// ---------------- helpers ----------------
__device__ __forceinline__ uint32_t smem_u32(const void* p) {
    uint32_t a;
    asm("{ .reg .u64 t; cvta.to.shared.u64 t, %1; cvt.u32.u64 %0, t; }" : "=r"(a) : "l"(p));
    return a;
}
__device__ __forceinline__ void ldsm4(uint32_t* r, uint32_t addr) {
    asm volatile("ldmatrix.sync.aligned.m8n8.x4.shared.b16 {%0,%1,%2,%3}, [%4];"
        : "=r"(r[0]), "=r"(r[1]), "=r"(r[2]), "=r"(r[3]) : "r"(addr));
}
__device__ __forceinline__ void mma16816(float* d, const uint32_t* a, uint32_t b0, uint32_t b1) {
    asm volatile("mma.sync.aligned.m16n8k16.row.col.f32.f16.f16.f32 "
        "{%0,%1,%2,%3}, {%4,%5,%6,%7}, {%8,%9}, {%0,%1,%2,%3};"
        : "+f"(d[0]), "+f"(d[1]), "+f"(d[2]), "+f"(d[3])
        : "r"(a[0]), "r"(a[1]), "r"(a[2]), "r"(a[3]), "r"(b0), "r"(b1));
}
__device__ __forceinline__ void cp16(uint32_t dst, const void* src) {
    asm volatile("cp.async.cg.shared.global [%0], [%1], 16;" :: "r"(dst), "l"(src));
}
#define CP_COMMIT() asm volatile("cp.async.commit_group;" ::: "memory")
#define CP_WAIT1()  asm volatile("cp.async.wait_group 1;" ::: "memory")
#define CP_WAIT0()  asm volatile("cp.async.wait_group 0;" ::: "memory")

__device__ __forceinline__ uint32_t pack2(float v0, float v1) {
    __half2 h = __floats2half2_rn(v0, v1);
    return *(uint32_t*)&h;
}

// ---------------------------------------------------------------------------
// Prologue: hx = x @ W1x ; hyb = y @ W1y + b1
// ---------------------------------------------------------------------------
__global__ void __launch_bounds__(256) prologue_gemm(
    const float* __restrict__ x, const float* __restrict__ y,
    const float* __restrict__ w1x, const float* __restrict__ w1y,
    const float* __restrict__ b1)
{
    const float* A = (blockIdx.z == 0) ? x   : y;
    const float* B = (blockIdx.z == 0) ? w1x : w1y;
    float*       C = (blockIdx.z == 0) ? g_hx : g_hyb;

    int m0 = blockIdx.y * 64, n0 = blockIdx.x * 64;
    __shared__ float sA[16][64 + 2];
    __shared__ float sB[16][64 + 2];
    int tid = threadIdx.x;
    int ty = tid >> 4, tx = tid & 15;

    float acc[4][4] = {};
    for (int k0 = 0; k0 < XD; k0 += 16) {
        #pragma unroll
        for (int s = 0; s < 4; s++) {
            int idx = tid + s * 256;
            int kk = idx & 15, m = idx >> 4;
            sA[kk][m] = A[(m0 + m) * XD + k0 + kk];
        }
        #pragma unroll
        for (int s = 0; s < 4; s++) {
            int idx = tid + s * 256;
            int nn = idx & 63, kk = idx >> 6;
            sB[kk][nn] = B[(k0 + kk) * HH + n0 + nn];
        }
        __syncthreads();
        #pragma unroll
        for (int kk = 0; kk < 16; kk++) {
            float a[4], b[4];
            #pragma unroll
            for (int u = 0; u < 4; u++) a[u] = sA[kk][ty * 4 + u];
            #pragma unroll
            for (int v = 0; v < 4; v++) b[v] = sB[kk][tx * 4 + v];
            #pragma unroll
            for (int u = 0; u < 4; u++)
                #pragma unroll
                for (int v = 0; v < 4; v++)
                    acc[u][v] = fmaf(a[u], b[v], acc[u][v]);
        }
        __syncthreads();
    }
    #pragma unroll
    for (int u = 0; u < 4; u++)
        #pragma unroll
        for (int v = 0; v < 4; v++) {
            int m = m0 + ty * 4 + u, n = n0 + tx * 4 + v;
            float val = acc[u][v];
            if (blockIdx.z == 1) val += b1[n];
            C[m * HH + n] = val;
        }
}

// ---------------------------------------------------------------------------
// W2 transpose to fp16
// ---------------------------------------------------------------------------
__global__ void __launch_bounds__(512) w2t_kernel(const float* __restrict__ w2)
{
    int k = blockIdx.x;
    int c = threadIdx.x;
    g_w2t[c * HH + k] = __float2half_rn(w2[k * HH + c]);
}

// ---------------------------------------------------------------------------
// Main HMMA kernel, plain fp16 inputs / fp32 acc.
// grid (16, 128), 256 threads, 8 warps (4 m x 2 n), 2 CTAs per SM.
// ---------------------------------------------------------------------------
__global__ void __launch_bounds__(256, 2) main_mma(
    const float* __restrict__ b2, const float* __restrict__ w3,
    const float* __restrict__ b3)
{
    extern __shared__ char smem[];
    uint32_t sb = smem_u32(smem);
    int tid = threadIdx.x, lane = tid & 31, wid = tid >> 5;
    int warp_m = wid >> 1, warp_n = wid & 1;
    int jt = blockIdx.x, it = blockIdx.y;

    float* hx_s  = (float*)(smem + OFF_HX);
    float* hyb_s = (float*)(smem + OFF_HYB);
    float* b2s   = (float*)(smem + OFF_B2);
    float* w3s   = (float*)(smem + OFF_W3);
    float* sRow  = (float*)(smem + OFF_ROW);
    float* sE    = (float*)(smem + OFF_E);

    // ---- group 0: stage hx (32 rows), hyb (4 rows), B stage for step 0 ----
    #pragma unroll
    for (int u = 0; u < 16; u++) {
        int idx = tid + u * 256;             // 4096 chunks of 16B
        int row = idx >> 7, q = idx & 127;
        cp16(sb + OFF_HX + (uint32_t)(row * (HXS*4) + q * 16),
             g_hx + (jt * 32 + row) * HH + q * 4);
    }
    #pragma unroll
    for (int u = 0; u < 2; u++) {
        int idx = tid + u * 256;             // 512 chunks
        int row = idx >> 7, q = idx & 127;
        cp16(sb + OFF_HYB + (uint32_t)(row * (HXS*4) + q * 16),
             g_hyb + (it * 4 + row) * HH + q * 4);
    }
    {   // B step 0 (nb=0, kc=0): 128 cols x 32 k halves = 512 chunks
        #pragma unroll
        for (int u = 0; u < 2; u++) {
            int idx = tid + u * 256;
            int col = idx >> 2, q = idx & 3;
            cp16(sb + OFF_B + (uint32_t)(col * 80 + q * 16),
                 g_w2t + col * HH + q * 8);
        }
    }
    CP_COMMIT();

    for (int c = tid; c < HH; c += 256) { b2s[c] = b2[c]; w3s[c] = w3[c]; }

    const int g  = lane >> 2;          // 0..7
    const int qk = (lane & 3) * 2;     // 0,2,4,6
    const float* hyr = hyb_s + warp_m * HXS;

    float ptl[4] = {0.f, 0.f, 0.f, 0.f};
    float acc[2][8][4];

    for (int s = 0; s < 64; s++) {
        int nb = s >> 4, kc = s & 15;
        if (kc == 0) {
            #pragma unroll
            for (int tm = 0; tm < 2; tm++)
                #pragma unroll
                for (int tn = 0; tn < 8; tn++)
                    #pragma unroll
                    for (int v = 0; v < 4; v++) acc[tm][tn][v] = 0.f;
        }

        // prefetch B for step s+1
        if (s < 63) {
            int nb2 = (s + 1) >> 4, kc2 = (s + 1) & 15;
            uint32_t stg = sb + OFF_B + ((s + 1) & 1) * BSTG;
            #pragma unroll
            for (int u = 0; u < 2; u++) {
                int idx = tid + u * 256;
                int col = idx >> 2, q = idx & 3;
                cp16(stg + (uint32_t)(col * 80 + q * 16),
                     g_w2t + (nb2 * 128 + col) * HH + kc2 * 32 + q * 8);
            }
            CP_COMMIT();
            CP_WAIT1();
        } else {
            CP_WAIT0();
        }
        __syncthreads();

        uint32_t stage = sb + OFF_B + (s & 1) * BSTG;

        #pragma unroll
        for (int ks = 0; ks < 2; ks++) {
            int kb = kc * 32 + ks * 16;
            // ---- A fragments in registers (fp16 cvt, no split) ----
            uint32_t ah[2][4];
            #pragma unroll
            for (int tm = 0; tm < 2; tm++) {
                int r0 = (warp_m * 32 + tm * 16 + g) & 31;       // j-local rows
                int r1 = (warp_m * 32 + tm * 16 + 8 + g) & 31;
                float2 x00 = *(const float2*)(hx_s + r0 * HXS + kb + qk);
                float2 x01 = *(const float2*)(hx_s + r0 * HXS + kb + qk + 8);
                float2 x10 = *(const float2*)(hx_s + r1 * HXS + kb + qk);
                float2 x11 = *(const float2*)(hx_s + r1 * HXS + kb + qk + 8);
                float2 y0  = *(const float2*)(hyr + kb + qk);
                float2 y1  = *(const float2*)(hyr + kb + qk + 8);
                ah[tm][0] = pack2(fmaxf(x00.x + y0.x, 0.f), fmaxf(x00.y + y0.y, 0.f));
                ah[tm][1] = pack2(fmaxf(x10.x + y0.x, 0.f), fmaxf(x10.y + y0.y, 0.f));
                ah[tm][2] = pack2(fmaxf(x01.x + y1.x, 0.f), fmaxf(x01.y + y1.y, 0.f));
                ah[tm][3] = pack2(fmaxf(x11.x + y1.x, 0.f), fmaxf(x11.y + y1.y, 0.f));
            }
            // ---- B tiles: paired ldsm.x4, 2 tn per op ----
            uint32_t bcol = (uint32_t)(warp_n * 64 + (lane & 7) + ((lane >> 4) & 1) * 8);
            uint32_t bchk = (uint32_t)(ks * 2 + ((lane >> 3) & 1));
            #pragma unroll
            for (int p = 0; p < 4; p++) {
                uint32_t addr = stage + (bcol + p * 16) * 80 + bchk * 16;
                uint32_t bh[4];
                ldsm4(bh, addr);
                #pragma unroll
                for (int tm = 0; tm < 2; tm++) {
                    mma16816(acc[tm][2*p],   ah[tm], bh[0], bh[1]);
                    mma16816(acc[tm][2*p+1], ah[tm], bh[2], bh[3]);
                }
            }
        }
        __syncthreads();

        // ---- end of nb block: fold into per-row scalars ----
        if (kc == 15) {
            #pragma unroll
            for (int tm = 0; tm < 2; tm++)
                #pragma unroll
                for (int tn = 0; tn < 8; tn++) {
                    int c0 = nb * 128 + warp_n * 64 + tn * 8 + (lane & 3) * 2;
                    float w3a = w3s[c0], w3b = w3s[c0 + 1];
                    float b2a = b2s[c0], b2b = b2s[c0 + 1];
                    float v0 = acc[tm][tn][0] + b2a;
                    float v1 = acc[tm][tn][1] + b2b;
                    float v2 = acc[tm][tn][2] + b2a;
                    float v3 = acc[tm][tn][3] + b2b;
                    ptl[tm*2+0] = fmaf(fmaxf(v0, 0.f), w3a, fmaf(fmaxf(v1, 0.f), w3b, ptl[tm*2+0]));
                    ptl[tm*2+1] = fmaf(fmaxf(v2, 0.f), w3a, fmaf(fmaxf(v3, 0.f), w3b, ptl[tm*2+1]));
                }
        }
    }

    // ---- reduce across the 4 column-thread groups (same rows) ----
    #pragma unroll
    for (int u = 0; u < 4; u++) {
        ptl[u] += __shfl_xor_sync(0xffffffffu, ptl[u], 1);
        ptl[u] += __shfl_xor_sync(0xffffffffu, ptl[u], 2);
    }
    if ((lane & 3) == 0) {
        int q = lane >> 2;
        sRow[(warp_m * 32 +  0 + q) * 2 + warp_n] = ptl[0];
        sRow[(warp_m * 32 +  8 + q) * 2 + warp_n] = ptl[1];
        sRow[(warp_m * 32 + 16 + q) * 2 + warp_n] = ptl[2];
        sRow[(warp_m * 32 + 24 + q) * 2 + warp_n] = ptl[3];
    }
    __syncthreads();

    if (tid < 128) {
        float ssum = sRow[tid * 2] + sRow[tid * 2 + 1] + b3[0];
        float T1 = (ssum > 20.f) ? ssum : log1pf(expf(ssum));
        int ii = it * 4 + (tid >> 5);
        int jj = jt * 32 + (tid & 31);
        if (ii == jj) g_t0[ii] = T1;
        sE[tid] = expf(T1);
    }
    __syncthreads();

    if (tid < 4) {
        float ssum = 0.f;
        #pragma unroll
        for (int jl = 0; jl < 32; jl++) ssum += sE[tid * 32 + jl];
        g_partial[(it * 4 + tid) * NJT + jt] = ssum;
    }
}

// ---------------------------------------------------------------------------
// Finalize
// ---------------------------------------------------------------------------
__global__ void finalize_kernel(float* __restrict__ out)
{
    int tid = threadIdx.x;
    float s = 0.f;
    #pragma unroll
    for (int jt = 0; jt < NJT; jt++) s += g_partial[tid * NJT + jt];
    float val = g_t0[tid] - logf(s);

    __shared__ float sh[512];
    sh[tid] = val;
    __syncthreads();
    for (int off = 256; off > 0; off >>= 1) {
        if (tid < off) sh[tid] += sh[tid + off];
        __syncthreads();
    }
    if (tid == 0) out[0] = sh[0] / 512.f + logf(512.f);
}

extern "C" void kernel_launch(void* const* d_in, const int* in_sizes, int n_in,
                              void* d_out, int out_size)
{
    const float* x   = (const float*)d_in[0];
    const float* y   = (const float*)d_in[1];
    const float* w1x = (const float*)d_in[2];
    const float* w1y = (const float*)d_in[3];
    const float* b1  = (const float*)d_in[4];
    const float* w2  = (const float*)d_in[5];
    const float* b2  = (const float*)d_in[6];
    const float* w3  = (const float*)d_in[7];
    const float* b3  = (const float*)d_in[8];
    float* out = (float*)d_out;

    cudaFuncSetAttribute(main_mma, cudaFuncAttributeMaxDynamicSharedMemorySize, SMEM_MAIN);

    dim3 g1(8, 8, 2);
    prologue_gemm<<<g1, 256>>>(x, y, w1x, w1y, b1);
    w2t_kernel<<<HH, HH>>>(w2);
    dim3 g2(NJT, NIT);
    main_mma<<<g2, 256, SMEM_MAIN>>>(b2, w3, b3);
    finalize_kernel<<<1, 512>>>(out);
}

// round 8
// speedup vs baseline: 7.6953x; 1.0399x over previous
#include <cuda_runtime.h>
#include <cuda_fp16.h>
#include <math.h>
#include <stdint.h>

#define NN 512
#define HH 512
#define XD 128
#define NJT 16
#define NIT 128

#define HXS 520            /* padded row stride (floats) for hx/hyb smem */

// smem byte offsets (per CTA total 111232 B -> 2 CTAs/SM)
#define OFF_HX   0          /* 32 rows x 520 x 4 = 66560 */
#define OFF_HYB  66560      /* 4 rows x 520 x 4 = 8320   */
#define OFF_B    74880      /* 3 stages x 10240          */
#define OFF_B2   105600
#define OFF_W3   107648
#define OFF_ROW  109696
#define OFF_E    110720
#define SMEM_MAIN 111232
#define BSTG 10240

// ---------------- device scratch ----------------
__device__ float  g_hx [NN*HH];
__device__ float  g_hyb[NN*HH];
__device__ __half g_w2t[HH*HH];    // W2^T fp16, [c*512 + k]
__device__ float  g_partial[NN*NJT];
__device__ float  g_t0[NN];

// ---------------- helpers ----------------
__device__ __forceinline__ uint32_t smem_u32(const void* p) {
    uint32_t a;
    asm("{ .reg .u64 t; cvta.to.shared.u64 t, %1; cvt.u32.u64 %0, t; }" : "=r"(a) : "l"(p));
    return a;
}
__device__ __forceinline__ void ldsm4(uint32_t* r, uint32_t addr) {
    asm volatile("ldmatrix.sync.aligned.m8n8.x4.shared.b16 {%0,%1,%2,%3}, [%4];"
        : "=r"(r[0]), "=r"(r[1]), "=r"(r[2]), "=r"(r[3]) : "r"(addr));
}
__device__ __forceinline__ void mma16816(float* d, const uint32_t* a, uint32_t b0, uint32_t b1) {
    asm volatile("mma.sync.aligned.m16n8k16.row.col.f32.f16.f16.f32 "
        "{%0,%1,%2,%3}, {%4,%5,%6,%7}, {%8,%9}, {%0,%1,%2,%3};"
        : "+f"(d[0]), "+f"(d[1]), "+f"(d[2]), "+f"(d[3])
        : "r"(a[0]), "r"(a[1]), "r"(a[2]), "r"(a[3]), "r"(b0), "r"(b1));
}
__device__ __forceinline__ void cp16(uint32_t dst, const void* src) {
    asm volatile("cp.async.cg.shared.global [%0], [%1], 16;" :: "r"(dst), "l"(src));
}
#define CP_COMMIT() asm volatile("cp.async.commit_group;" ::: "memory")
#define CP_WAIT1()  asm volatile("cp.async.wait_group 1;" ::: "memory")
#define CP_WAIT0()  asm volatile("cp.async.wait_group 0;" ::: "memory")

__device__ __forceinline__ uint32_t pack2(float v0, float v1) {
    __half2 h = __floats2half2_rn(v0, v1);
    return *(uint32_t*)&h;
}

// ---------------------------------------------------------------------------
// Prologue: hx = x @ W1x ; hyb = y @ W1y + b1
// ---------------------------------------------------------------------------
__global__ void __launch_bounds__(256) prologue_gemm(
    const float* __restrict__ x, const float* __restrict__ y,
    const float* __restrict__ w1x, const float* __restrict__ w1y,
    const float* __restrict__ b1)
{
    const float* A = (blockIdx.z == 0) ? x   : y;
    const float* B = (blockIdx.z == 0) ? w1x : w1y;
    float*       C = (blockIdx.z == 0) ? g_hx : g_hyb;

    int m0 = blockIdx.y * 64, n0 = blockIdx.x * 64;
    __shared__ float sA[16][64 + 2];
    __shared__ float sB[16][64 + 2];
    int tid = threadIdx.x;
    int ty = tid >> 4, tx = tid & 15;

    float acc[4][4] = {};
    for (int k0 = 0; k0 < XD; k0 += 16) {
        #pragma unroll
        for (int s = 0; s < 4; s++) {
            int idx = tid + s * 256;
            int kk = idx & 15, m = idx >> 4;
            sA[kk][m] = A[(m0 + m) * XD + k0 + kk];
        }
        #pragma unroll
        for (int s = 0; s < 4; s++) {
            int idx = tid + s * 256;
            int nn = idx & 63, kk = idx >> 6;
            sB[kk][nn] = B[(k0 + kk) * HH + n0 + nn];
        }
        __syncthreads();
        #pragma unroll
        for (int kk = 0; kk < 16; kk++) {
            float a[4], b[4];
            #pragma unroll
            for (int u = 0; u < 4; u++) a[u] = sA[kk][ty * 4 + u];
            #pragma unroll
            for (int v = 0; v < 4; v++) b[v] = sB[kk][tx * 4 + v];
            #pragma unroll
            for (int u = 0; u < 4; u++)
                #pragma unroll
                for (int v = 0; v < 4; v++)
                    acc[u][v] = fmaf(a[u], b[v], acc[u][v]);
        }
        __syncthreads();
    }
    #pragma unroll
    for (int u = 0; u < 4; u++)
        #pragma unroll
        for (int v = 0; v < 4; v++) {
            int m = m0 + ty * 4 + u, n = n0 + tx * 4 + v;
            float val = acc[u][v];
            if (blockIdx.z == 1) val += b1[n];
            C[m * HH + n] = val;
        }
}

// ---------------------------------------------------------------------------
// W2 transpose to fp16
// ---------------------------------------------------------------------------
__global__ void __launch_bounds__(512) w2t_kernel(const float* __restrict__ w2)
{
    int k = blockIdx.x;
    int c = threadIdx.x;
    g_w2t[c * HH + k] = __float2half_rn(w2[k * HH + c]);
}

// ---------------------------------------------------------------------------
// Main HMMA kernel, fp16 in / fp32 acc. grid (16, 128), 256 thr, 8 warps
// (4 m x 2 n), 2 CTAs/SM. 3-stage B ring (prefetch dist 2, ONE sync/step),
// software-pipelined A-fragment build.
// ---------------------------------------------------------------------------
__global__ void __launch_bounds__(256, 2) main_mma(
    const float* __restrict__ b2, const float* __restrict__ w3,
    const float* __restrict__ b3)
{
    extern __shared__ char smem[];
    uint32_t sb = smem_u32(smem);
    int tid = threadIdx.x, lane = tid & 31, wid = tid >> 5;
    int warp_m = wid >> 1, warp_n = wid & 1;
    int jt = blockIdx.x, it = blockIdx.y;

    float* hx_s  = (float*)(smem + OFF_HX);
    float* hyb_s = (float*)(smem + OFF_HYB);
    float* b2s   = (float*)(smem + OFF_B2);
    float* w3s   = (float*)(smem + OFF_W3);
    float* sRow  = (float*)(smem + OFF_ROW);
    float* sE    = (float*)(smem + OFF_E);

    // ---- group 0: hx (32 rows) + hyb (4 rows) + B stage 0 ----
    #pragma unroll
    for (int u = 0; u < 16; u++) {
        int idx = tid + u * 256;
        int row = idx >> 7, q = idx & 127;
        cp16(sb + OFF_HX + (uint32_t)(row * (HXS*4) + q * 16),
             g_hx + (jt * 32 + row) * HH + q * 4);
    }
    #pragma unroll
    for (int u = 0; u < 2; u++) {
        int idx = tid + u * 256;
        int row = idx >> 7, q = idx & 127;
        cp16(sb + OFF_HYB + (uint32_t)(row * (HXS*4) + q * 16),
             g_hyb + (it * 4 + row) * HH + q * 4);
    }
    #pragma unroll
    for (int u = 0; u < 2; u++) {            // B step 0 (nb=0,kc=0)
        int idx = tid + u * 256;
        int col = idx >> 2, q = idx & 3;
        cp16(sb + OFF_B + (uint32_t)(col * 80 + q * 16),
             g_w2t + col * HH + q * 8);
    }
    CP_COMMIT();
    // ---- group 1: B stage 1 (step 1: nb=0, kc=1) ----
    #pragma unroll
    for (int u = 0; u < 2; u++) {
        int idx = tid + u * 256;
        int col = idx >> 2, q = idx & 3;
        cp16(sb + OFF_B + BSTG + (uint32_t)(col * 80 + q * 16),
             g_w2t + col * HH + 32 + q * 8);
    }
    CP_COMMIT();

    for (int c = tid; c < HH; c += 256) { b2s[c] = b2[c]; w3s[c] = w3[c]; }

    const int g  = lane >> 2;          // 0..7
    const int qk = (lane & 3) * 2;     // 0,2,4,6
    const float* hyr = hyb_s + warp_m * HXS;

    float ptl[4] = {0.f, 0.f, 0.f, 0.f};
    float acc[2][8][4];
    uint32_t ah_cur[2][4], ah_nxt[2][4];

    const uint32_t bcol = (uint32_t)(warp_n * 64 + (lane & 7) + ((lane >> 4) & 1) * 8);
    const uint32_t bchk_base = (uint32_t)((lane >> 3) & 1);

    // A-fragment builder for k-block base kb
    #define BUILD_A(dst, kb_) do {                                              \
        int kb = (kb_);                                                         \
        _Pragma("unroll")                                                       \
        for (int tm = 0; tm < 2; tm++) {                                        \
            int r0 = (warp_m * 32 + tm * 16 + g) & 31;                          \
            int r1 = (warp_m * 32 + tm * 16 + 8 + g) & 31;                      \
            float2 x00 = *(const float2*)(hx_s + r0 * HXS + kb + qk);           \
            float2 x01 = *(const float2*)(hx_s + r0 * HXS + kb + qk + 8);       \
            float2 x10 = *(const float2*)(hx_s + r1 * HXS + kb + qk);           \
            float2 x11 = *(const float2*)(hx_s + r1 * HXS + kb + qk + 8);       \
            float2 y0  = *(const float2*)(hyr + kb + qk);                       \
            float2 y1  = *(const float2*)(hyr + kb + qk + 8);                   \
            dst[tm][0] = pack2(fmaxf(x00.x + y0.x, 0.f), fmaxf(x00.y + y0.y, 0.f)); \
            dst[tm][1] = pack2(fmaxf(x10.x + y0.x, 0.f), fmaxf(x10.y + y0.y, 0.f)); \
            dst[tm][2] = pack2(fmaxf(x01.x + y1.x, 0.f), fmaxf(x01.y + y1.y, 0.f)); \
            dst[tm][3] = pack2(fmaxf(x11.x + y1.x, 0.f), fmaxf(x11.y + y1.y, 0.f)); \
        }                                                                       \
    } while (0)

    #define MMA_BLOCK(ah, stage, ks) do {                                       \
        uint32_t bchk = (uint32_t)((ks) * 2) + bchk_base;                       \
        _Pragma("unroll")                                                       \
        for (int p = 0; p < 4; p++) {                                           \
            uint32_t addr = (stage) + (bcol + p * 16) * 80 + bchk * 16;         \
            uint32_t bh[4];                                                     \
            ldsm4(bh, addr);                                                    \
            _Pragma("unroll")                                                   \
            for (int tm = 0; tm < 2; tm++) {                                    \
                mma16816(acc[tm][2*p],   ah[tm], bh[0], bh[1]);                 \
                mma16816(acc[tm][2*p+1], ah[tm], bh[2], bh[3]);                 \
            }                                                                   \
        }                                                                       \
    } while (0)

    // wait for group 0 (hx/hyb/stage0); group 1 may stay in flight
    CP_WAIT1();
    __syncthreads();

    BUILD_A(ah_cur, 0);   // (s=0, ks=0)

    for (int s = 0; s < 64; s++) {
        int nb = s >> 4, kc = s & 15;
        (void)nb;

        if (s) {
            if (s < 63) { CP_WAIT1(); } else { CP_WAIT0(); }
            __syncthreads();
        }

        // prefetch B for step s+2 into ring slot (s+2)%3 (read last at s-1)
        if (s < 62) {
            int s2 = s + 2;
            int nb2 = s2 >> 4, kc2 = s2 & 15;
            uint32_t stg = sb + OFF_B + (uint32_t)((s2 % 3) * BSTG);
            #pragma unroll
            for (int u = 0; u < 2; u++) {
                int idx = tid + u * 256;
                int col = idx >> 2, q = idx & 3;
                cp16(stg + (uint32_t)(col * 80 + q * 16),
                     g_w2t + (nb2 * 128 + col) * HH + kc2 * 32 + q * 8);
            }
            CP_COMMIT();
        }

        if (kc == 0) {
            #pragma unroll
            for (int tm = 0; tm < 2; tm++)
                #pragma unroll
                for (int tn = 0; tn < 8; tn++)
                    #pragma unroll
                    for (int v = 0; v < 4; v++) acc[tm][tn][v] = 0.f;
        }

        uint32_t stage = sb + OFF_B + (uint32_t)((s % 3) * BSTG);

        // ks=0: MMA with ah_cur; build ah_nxt (this step, ks=1) under the MMAs
        BUILD_A(ah_nxt, kc * 32 + 16);
        MMA_BLOCK(ah_cur, stage, 0);
        // ks=1: MMA with ah_nxt; build ah_cur for (s+1, ks=0) under the MMAs
        BUILD_A(ah_cur, ((s + 1) & 15) * 32);
        MMA_BLOCK(ah_nxt, stage, 1);

        // ---- end of nb block: fold into per-row scalars ----
        if (kc == 15) {
            #pragma unroll
            for (int tm = 0; tm < 2; tm++)
                #pragma unroll
                for (int tn = 0; tn < 8; tn++) {
                    int c0 = nb * 128 + warp_n * 64 + tn * 8 + (lane & 3) * 2;
                    float w3a = w3s[c0], w3b = w3s[c0 + 1];
                    float b2a = b2s[c0], b2b = b2s[c0 + 1];
                    float v0 = acc[tm][tn][0] + b2a;
                    float v1 = acc[tm][tn][1] + b2b;
                    float v2 = acc[tm][tn][2] + b2a;
                    float v3 = acc[tm][tn][3] + b2b;
                    ptl[tm*2+0] = fmaf(fmaxf(v0, 0.f), w3a, fmaf(fmaxf(v1, 0.f), w3b, ptl[tm*2+0]));
                    ptl[tm*2+1] = fmaf(fmaxf(v2, 0.f), w3a, fmaf(fmaxf(v3, 0.f), w3b, ptl[tm*2+1]));
                }
        }
    }

    // ---- reduce across the 4 column-thread groups (same rows) ----
    #pragma unroll
    for (int u = 0; u < 4; u++) {
        ptl[u] += __shfl_xor_sync(0xffffffffu, ptl[u], 1);
        ptl[u] += __shfl_xor_sync(0xffffffffu, ptl[u], 2);
    }
    __syncthreads();
    if ((lane & 3) == 0) {
        int q = lane >> 2;
        sRow[(warp_m * 32 +  0 + q) * 2 + warp_n] = ptl[0];
        sRow[(warp_m * 32 +  8 + q) * 2 + warp_n] = ptl[1];
        sRow[(warp_m * 32 + 16 + q) * 2 + warp_n] = ptl[2];
        sRow[(warp_m * 32 + 24 + q) * 2 + warp_n] = ptl[3];
    }
    __syncthreads();

    if (tid < 128) {
        float ssum = sRow[tid * 2] + sRow[tid * 2 + 1] + b3[0];
        float T1 = (ssum > 20.f) ? ssum : log1pf(expf(ssum));
        int ii = it * 4 + (tid >> 5);
        int jj = jt * 32 + (tid & 31);
        if (ii == jj) g_t0[ii] = T1;
        sE[tid] = expf(T1);
    }
    __syncthreads();

    if (tid < 4) {
        float ssum = 0.f;
        #pragma unroll
        for (int jl = 0; jl < 32; jl++) ssum += sE[tid * 32 + jl];
        g_partial[(it * 4 + tid) * NJT + jt] = ssum;
    }
}

// ---------------------------------------------------------------------------
// Finalize
// ---------------------------------------------------------------------------
__global__ void finalize_kernel(float* __restrict__ out)
{
    int tid = threadIdx.x;
    float s = 0.f;
    #pragma unroll
    for (int jt = 0; jt < NJT; jt++) s += g_partial[tid * NJT + jt];
    float val = g_t0[tid] - logf(s);

    __shared__ float sh[512];
    sh[tid] = val;
    __syncthreads();
    for (int off = 256; off > 0; off >>= 1) {
        if (tid < off) sh[tid] += sh[tid + off];
        __syncthreads();
    }
    if (tid == 0) out[0] = sh[0] / 512.f + logf(512.f);
}

extern "C" void kernel_launch(void* const* d_in, const int* in_sizes, int n_in,
                              void* d_out, int out_size)
{
    const float* x   = (const float*)d_in[0];
    const float* y   = (const float*)d_in[1];
    const float* w1x = (const float*)d_in[2];
    const float* w1y = (const float*)d_in[3];
    const float* b1  = (const float*)d_in[4];
    const float* w2  = (const float*)d_in[5];
    const float* b2  = (const float*)d_in[6];
    const float* w3  = (const float*)d_in[7];
    const float* b3  = (const float*)d_in[8];
    float* out = (float*)d_out;

    cudaFuncSetAttribute(main_mma, cudaFuncAttributeMaxDynamicSharedMemorySize, SMEM_MAIN);

    dim3 g1(8, 8, 2);
    prologue_gemm<<<g1, 256>>>(x, y, w1x, w1y, b1);
    w2t_kernel<<<HH, HH>>>(w2);
    dim3 g2(NJT, NIT);
    main_mma<<<g2, 256, SMEM_MAIN>>>(b2, w3, b3);
    finalize_kernel<<<1, 512>>>(out);
}